// round 4
// baseline (speedup 1.0000x reference)
#include <cuda_runtime.h>
#include <math_constants.h>

// Chamfer distance, B=16, N=M=4096, 3-D points.
// result = mean_n min_m d(x1_n, x2_m) + mean_m min_n d(x2_m, x1_n)
// d = |x|^2 + |y|^2 - 2 x.y, clamped at 0. sq1 and the clamp are folded
// outside the min loop (both commute with min).
// 4 queries per thread: LDS of staged targets amortized so total issue cost
// (2.75 cyc/pair) sits under the FFMA2-pipe floor (3.0 cyc/pair).

#define BATCH      16
#define NPTS       4096
#define CHUNK      1024        // targets staged per smem tile
#define TPB        128         // threads per block
#define QPT        4           // queries per thread
#define QPB        (TPB * QPT) // queries per block = 512
#define OUT_SCALE  (1.0f / 65536.0f)   // 1/(B*N), same for both directions

// ---- packed f32x2 helpers (sm_10x) -----------------------------------------
__device__ __forceinline__ unsigned long long pk2(float lo, float hi) {
    unsigned long long r;
    asm("mov.b64 %0, {%1, %2};" : "=l"(r) : "f"(lo), "f"(hi));
    return r;
}
__device__ __forceinline__ void unpk2(unsigned long long v, float& lo, float& hi) {
    asm("mov.b64 {%0, %1}, %2;" : "=f"(lo), "=f"(hi) : "l"(v));
}
__device__ __forceinline__ unsigned long long fma2(unsigned long long a,
                                                   unsigned long long b,
                                                   unsigned long long c) {
    unsigned long long d;
    asm("fma.rn.f32x2 %0, %1, %2, %3;" : "=l"(d) : "l"(a), "l"(b), "l"(c));
    return d;
}

__global__ void chamfer_zero_kernel(float* out) { out[0] = 0.0f; }

__global__ void __launch_bounds__(TPB)
chamfer_main_kernel(const float* __restrict__ xyz1,
                    const float* __restrict__ xyz2,
                    float* __restrict__ out) {
    __shared__ float sx[CHUNK];
    __shared__ float sy[CHUNK];
    __shared__ float sz[CHUNK];
    __shared__ float ss[CHUNK];
    __shared__ float red[4];

    const int dir = blockIdx.y;                 // 0: q=xyz1,t=xyz2; 1: swapped
    const int b   = blockIdx.x / (NPTS / QPB);
    const int qb  = blockIdx.x % (NPTS / QPB);
    const int tid = threadIdx.x;

    const float* qsrc = dir ? xyz2 : xyz1;
    const float* tsrc = dir ? xyz1 : xyz2;
    const float* tbase = tsrc + (size_t)b * NPTS * 3;

    // ---- per-thread query points (QPT, strided by TPB) ----
    float qx[QPT], qy[QPT], qz[QPT], sq[QPT];
    unsigned long long Cx[QPT], Cy[QPT], Cz[QPT];
    #pragma unroll
    for (int k = 0; k < QPT; ++k) {
        const int qi = qb * QPB + tid + k * TPB;
        const float* qp = qsrc + ((size_t)b * NPTS + qi) * 3;
        qx[k] = qp[0]; qy[k] = qp[1]; qz[k] = qp[2];
        sq[k] = fmaf(qx[k], qx[k], fmaf(qy[k], qy[k], qz[k] * qz[k]));
        Cx[k] = pk2(-2.0f * qx[k], -2.0f * qx[k]);
        Cy[k] = pk2(-2.0f * qy[k], -2.0f * qy[k]);
        Cz[k] = pk2(-2.0f * qz[k], -2.0f * qz[k]);
    }

    float mn[QPT][4];
    #pragma unroll
    for (int k = 0; k < QPT; ++k)
        #pragma unroll
        for (int t = 0; t < 4; ++t) mn[k][t] = CUDART_INF_F;

    for (int c0 = 0; c0 < NPTS; c0 += CHUNK) {
        // ---- stage CHUNK targets into smem as SoA (x, y, z, |t|^2) ----
        for (int i = tid; i < CHUNK; i += TPB) {
            const float* t = tbase + (size_t)(c0 + i) * 3;
            float x = t[0], y = t[1], z = t[2];
            sx[i] = x;
            sy[i] = y;
            sz[i] = z;
            ss[i] = fmaf(x, x, fmaf(y, y, z * z));
        }
        __syncthreads();

        const float4* x4 = reinterpret_cast<const float4*>(sx);
        const float4* y4 = reinterpret_cast<const float4*>(sy);
        const float4* z4 = reinterpret_cast<const float4*>(sz);
        const float4* s4 = reinterpret_cast<const float4*>(ss);

        // ---- 4 targets x QPT queries per iteration, packed f32x2 FMAs ----
        #pragma unroll 4
        for (int j = 0; j < CHUNK / 4; ++j) {
            const float4 X = x4[j];
            const float4 Y = y4[j];
            const float4 Z = z4[j];
            const float4 S = s4[j];

            const unsigned long long X01 = pk2(X.x, X.y), X23 = pk2(X.z, X.w);
            const unsigned long long Y01 = pk2(Y.x, Y.y), Y23 = pk2(Y.z, Y.w);
            const unsigned long long Z01 = pk2(Z.x, Z.y), Z23 = pk2(Z.z, Z.w);
            const unsigned long long S01 = pk2(S.x, S.y), S23 = pk2(S.z, S.w);

            #pragma unroll
            for (int k = 0; k < QPT; ++k) {
                // cand = sq2 - 2*(q . t)    (sq[k] added after the loop)
                unsigned long long c01 = fma2(Cz[k], Z01, S01);
                unsigned long long c23 = fma2(Cz[k], Z23, S23);
                c01 = fma2(Cy[k], Y01, c01);
                c23 = fma2(Cy[k], Y23, c23);
                c01 = fma2(Cx[k], X01, c01);
                c23 = fma2(Cx[k], X23, c23);

                float lo, hi;
                unpk2(c01, lo, hi);
                mn[k][0] = fminf(mn[k][0], lo);
                mn[k][1] = fminf(mn[k][1], hi);
                unpk2(c23, lo, hi);
                mn[k][2] = fminf(mn[k][2], lo);
                mn[k][3] = fminf(mn[k][3], hi);
            }
        }
        __syncthreads();
    }

    // dist = max(sq1 + min_m cand, 0), summed over this thread's queries
    float v = 0.0f;
    #pragma unroll
    for (int k = 0; k < QPT; ++k) {
        const float dmin = fminf(fminf(mn[k][0], mn[k][1]),
                                 fminf(mn[k][2], mn[k][3]));
        v += fmaxf(sq[k] + dmin, 0.0f);
    }

    // ---- block reduction (4 warps) ----
    #pragma unroll
    for (int off = 16; off > 0; off >>= 1)
        v += __shfl_down_sync(0xffffffffu, v, off);
    const int warp = tid >> 5, lane = tid & 31;
    if (lane == 0) red[warp] = v;
    __syncthreads();
    if (warp == 0) {
        v = (lane < 4) ? red[lane] : 0.0f;
        #pragma unroll
        for (int off = 2; off > 0; off >>= 1)
            v += __shfl_down_sync(0xffffffffu, v, off);
        if (lane == 0) atomicAdd(out, v * OUT_SCALE);
    }
}

extern "C" void kernel_launch(void* const* d_in, const int* in_sizes, int n_in,
                              void* d_out, int out_size) {
    const float* xyz1 = (const float*)d_in[0];
    const float* xyz2 = (const float*)d_in[1];
    float* out = (float*)d_out;

    chamfer_zero_kernel<<<1, 1>>>(out);
    dim3 grid(BATCH * (NPTS / QPB), 2);
    chamfer_main_kernel<<<grid, TPB>>>(xyz1, xyz2, out);
}